// round 16
// baseline (speedup 1.0000x reference)
#include <cuda_runtime.h>
#include <cuda_fp16.h>
#include <cstdint>
#include <math.h>

// ---------------------------------------------------------------------------
// Problem constants
// ---------------------------------------------------------------------------
#define NNODES 8192
#define FDIM   16
#define HDIM   64
#define GSEG   256
#define LNEPS  1e-3f
#define ASCALE 8192.0f
#define AINV   (1.0f / 8192.0f)

#define NSPLIT 2
#define KSPLIT (NNODES / NSPLIT)   // 4096
#define BM 128

// GEMM (fp16 m16n8k16, 512 threads, 16 warps: 4m x 2n x 2kg)
#define BK2 64
#define NIT2 (KSPLIT / BK2)        // 64
#define LDH 72                     // half pitch (144 B), proven conflict-free
#define ST2A (BM * LDH * 2)        // 18432 B
#define ST2B (64 * LDH * 2)        // 9216 B
#define NST2 4
#define SMEM2 (NST2 * (ST2A + ST2B))   // 110592 B

// prep kernel block ranges
#define PREP_CONV 2048
#define PREP_Y0T  1024
#define PREP_GRID (PREP_CONV + PREP_Y0T + GSEG)   // 3328

// ---------------------------------------------------------------------------
// Device scratch
// ---------------------------------------------------------------------------
__device__ __half dAh[(size_t)NNODES * NNODES];   // A * 8192 fp16 (128 MB)
__device__ __half dY0Th[HDIM * NNODES];           // (X@W0)^T fp16
__device__ __half dY1Th[HDIM * NNODES];           // (h0@W1)^T fp16
__device__ float dZP[NSPLIT * NNODES * HDIM];     // split-K partials
__device__ float dH0[NNODES * HDIM];
__device__ float dG[GSEG * HDIM];
__device__ float dZsum[GSEG];
__device__ float dZnum[GSEG * 3];
__device__ int dCnt1[NNODES / BM];                // completion counters G1
__device__ int dCnt2[NNODES / BM];                // completion counters G2

// ---------------------------------------------------------------------------
// PTX helpers
// ---------------------------------------------------------------------------
__device__ __forceinline__ void cpa16(uint32_t dst, const void *src) {
    asm volatile("cp.async.cg.shared.global [%0], [%1], 16;" ::"r"(dst), "l"(src));
}
__device__ __forceinline__ void cpa_commit() {
    asm volatile("cp.async.commit_group;");
}
__device__ __forceinline__ void ldsm4(uint32_t &r0, uint32_t &r1, uint32_t &r2,
                                      uint32_t &r3, uint32_t addr) {
    asm volatile("ldmatrix.sync.aligned.m8n8.x4.shared.b16 {%0,%1,%2,%3}, [%4];"
                 : "=r"(r0), "=r"(r1), "=r"(r2), "=r"(r3) : "r"(addr));
}
__device__ __forceinline__ void mma_f16(float c[4], const uint32_t a[4],
                                        const uint32_t b[2]) {
    asm volatile(
        "mma.sync.aligned.m16n8k16.row.col.f32.f16.f16.f32 "
        "{%0,%1,%2,%3}, {%4,%5,%6,%7}, {%8,%9}, {%0,%1,%2,%3};"
        : "+f"(c[0]), "+f"(c[1]), "+f"(c[2]), "+f"(c[3])
        : "r"(a[0]), "r"(a[1]), "r"(a[2]), "r"(a[3]), "r"(b[0]), "r"(b[1]));
}

// ---------------------------------------------------------------------------
// prep: conv (Ah) + y0t (Y0Th) + zseg (stats) + zero dG/counters, one launch
// ---------------------------------------------------------------------------
__global__ void __launch_bounds__(256)
prep_kernel(const float *__restrict__ A, __half *__restrict__ Ah,
            const float *__restrict__ X, const float *__restrict__ W0,
            const int *__restrict__ I) {
    const int bid = blockIdx.x;
    const int tid = threadIdx.x;

    if (bid < PREP_CONV) {
        const size_t stride = (size_t)PREP_CONV * 256 * 8;
        size_t base = ((size_t)bid * 256 + tid) * 8;
        const size_t total = (size_t)NNODES * NNODES;
        for (size_t i = base; i < total; i += stride) {
            float4 v0 = *(const float4 *)(A + i);
            float4 v1 = *(const float4 *)(A + i + 4);
            __half2 h[4];
            h[0] = __floats2half2_rn(v0.x * ASCALE, v0.y * ASCALE);
            h[1] = __floats2half2_rn(v0.z * ASCALE, v0.w * ASCALE);
            h[2] = __floats2half2_rn(v1.x * ASCALE, v1.y * ASCALE);
            h[3] = __floats2half2_rn(v1.z * ASCALE, v1.w * ASCALE);
            *(uint4 *)(Ah + i) = *(uint4 *)h;
        }
    } else if (bid < PREP_CONV + PREP_Y0T) {
        __shared__ float W0s[FDIM][HDIM];
        __shared__ float ybuf[8][68];
        int lane = tid & 31, ty = tid >> 5;
#pragma unroll
        for (int j = 0; j < 4; j++) {
            int idx = tid + 256 * j;
            W0s[idx >> 6][idx & 63] = W0[idx];
        }
        __syncthreads();
        int row0 = (bid - PREP_CONV) * 8;
        int row = row0 + ty;
        float a0 = 0.f, a1 = 0.f;
#pragma unroll
        for (int f = 0; f < FDIM; f++) {
            float xf = X[row * FDIM + f];
            a0 += xf * W0s[f][lane];
            a1 += xf * W0s[f][lane + 32];
        }
        ybuf[ty][lane] = a0;
        ybuf[ty][lane + 32] = a1;
        __syncthreads();
#pragma unroll
        for (int k = 0; k < 2; k++) {
            int v = tid + 256 * k;
            int n = v >> 3, r = v & 7;
            dY0Th[(size_t)n * NNODES + row0 + r] = __float2half_rn(ybuf[r][n]);
        }
    } else {
        __shared__ int sb[2];
        __shared__ float red[256];
        int g = bid - (PREP_CONV + PREP_Y0T);
        int t = tid;
        if (t == 0) {
            int a = 0, b = NNODES;
            while (a < b) { int m = (a + b) >> 1; if (I[m] < g) a = m + 1; else b = m; }
            sb[0] = a;
            b = NNODES;
            while (a < b) { int m = (a + b) >> 1; if (I[m] < g + 1) a = m + 1; else b = m; }
            sb[1] = a;
        }
        if (t < HDIM) dG[g * HDIM + t] = 0.f;
        if (g < NNODES / BM && t == 64) { dCnt1[g] = 0; dCnt2[g] = 0; }
        __syncthreads();
        int lo = sb[0], hi = sb[1];

        float zmax = 0.f;
        for (int i = lo + t; i < hi; i += 256)
            zmax = fmaxf(zmax, log1pf(fmaxf(X[i * FDIM], 0.f)));
        red[t] = zmax;
        __syncthreads();
        for (int s = 128; s > 0; s >>= 1) {
            if (t < s) red[t] = fmaxf(red[t], red[t + s]);
            __syncthreads();
        }
        zmax = red[0];
        __syncthreads();

        float se = 0.f, s0 = 0.f, s1 = 0.f, s2 = 0.f;
        for (int i = lo + t; i < hi; i += 256) {
            float z = log1pf(fmaxf(X[i * FDIM], 0.f));
            float w = expf(z - zmax);
            se += w;
            s0 += w * X[i * FDIM + 13];
            s1 += w * X[i * FDIM + 14];
            s2 += w * X[i * FDIM + 15];
        }
        float vals[4] = {se, s0, s1, s2};
#pragma unroll
        for (int q = 0; q < 4; q++) {
            red[t] = vals[q];
            __syncthreads();
            for (int s = 128; s > 0; s >>= 1) {
                if (t < s) red[t] += red[t + s];
                __syncthreads();
            }
            vals[q] = red[0];
            __syncthreads();
        }
        if (t == 0) {
            dZsum[g] = vals[0];
            dZnum[g * 3 + 0] = vals[1];
            dZnum[g * 3 + 1] = vals[2];
            dZnum[g * 3 + 2] = vals[3];
        }
    }
}

// ---------------------------------------------------------------------------
// Shared GEMM mainloop (R15 champion): 512 thr, 16 warps = 4m x 2n x 2kg
// Produces c[2][4][4] per kg0-warp after reduction; partial written to dZP.
// ---------------------------------------------------------------------------
#define GEMM_MAIN(AhP, BhP)                                                   \
    extern __shared__ char smc[];                                             \
    char *As = smc;                                                           \
    char *Bs = smc + NST2 * ST2A;                                             \
    const int tid = threadIdx.x;                                              \
    const int lane = tid & 31, wid = tid >> 5;                                \
    const int wm = wid & 3;                                                   \
    const int wn = (wid >> 2) & 1;                                            \
    const int kg = wid >> 3;                                                  \
    const int m0 = blockIdx.x * BM;                                           \
    const int kbeg = blockIdx.y * KSPLIT;                                     \
    float c[2][4][4] = {};                                                    \
    const int arw = tid >> 3;                                                 \
    const int ach = tid & 7;                                                  \
    const __half *gA1 = (AhP) + (size_t)(m0 + arw) * NNODES + kbeg + ach * 8; \
    const __half *gA2 = gA1 + (size_t)64 * NNODES;                            \
    const uint32_t sA1 = (uint32_t)__cvta_generic_to_shared(As) + arw * (LDH * 2) + ach * 16; \
    const uint32_t sA2 = sA1 + 64 * (LDH * 2);                                \
    const __half *gB = (BhP) + (size_t)arw * NNODES + kbeg + ach * 8;         \
    const uint32_t sB = (uint32_t)__cvta_generic_to_shared(Bs) + arw * (LDH * 2) + ach * 16; \
    const int arow = wm * 32 + (lane & 7) + ((lane >> 3) & 1) * 8;            \
    const int brow_ = wn * 32 + (lane & 7) + ((lane >> 3) & 1) * 8;           \
    const int kh = ((lane >> 4) & 1) * 8;                                     \
    for (int s = 0; s < NST2 - 1; s++) {                                      \
        int buf = s % NST2;                                                   \
        size_t koff = (size_t)s * BK2;                                        \
        cpa16(sA1 + buf * ST2A, gA1 + koff);                                  \
        cpa16(sA2 + buf * ST2A, gA2 + koff);                                  \
        cpa16(sB + buf * ST2B, gB + koff);                                    \
        cpa_commit();                                                         \
    }                                                                         \
    for (int it = 0; it < NIT2; ++it) {                                       \
        asm volatile("cp.async.wait_group 2;" ::: "memory");                  \
        __syncthreads();                                                      \
        if (it + NST2 - 1 < NIT2) {                                           \
            int buf = (it + NST2 - 1) % NST2;                                 \
            size_t koff = (size_t)(it + NST2 - 1) * BK2;                      \
            cpa16(sA1 + buf * ST2A, gA1 + koff);                              \
            cpa16(sA2 + buf * ST2A, gA2 + koff);                              \
            cpa16(sB + buf * ST2B, gB + koff);                                \
        }                                                                     \
        cpa_commit();                                                         \
        const int buf = it % NST2;                                            \
        uint32_t abase = (uint32_t)__cvta_generic_to_shared(As) + buf * ST2A; \
        uint32_t bbase = (uint32_t)__cvta_generic_to_shared(Bs) + buf * ST2B; \
        _Pragma("unroll") for (int kq = 0; kq < 2; kq++) {                    \
            int kb = (kg * 2 + kq) * 16 + kh;                                 \
            uint32_t a[2][4], b[4][2];                                        \
            _Pragma("unroll") for (int mi = 0; mi < 2; mi++) {                \
                uint32_t addr = abase + (arow + mi * 16) * (LDH * 2) + kb * 2; \
                ldsm4(a[mi][0], a[mi][1], a[mi][2], a[mi][3], addr);          \
            }                                                                 \
            _Pragma("unroll") for (int p = 0; p < 2; p++) {                   \
                uint32_t addr = bbase + (brow_ + p * 16) * (LDH * 2) + kb * 2; \
                uint32_t r0, r1, r2, r3;                                      \
                ldsm4(r0, r1, r2, r3, addr);                                  \
                b[p * 2][0] = r0; b[p * 2 + 1][0] = r1;                       \
                b[p * 2][1] = r2; b[p * 2 + 1][1] = r3;                       \
            }                                                                 \
            _Pragma("unroll") for (int mi = 0; mi < 2; mi++)                  \
                _Pragma("unroll") for (int nj = 0; nj < 4; nj++)              \
                    mma_f16(c[mi][nj], a[mi], b[nj]);                         \
        }                                                                     \
    }                                                                         \
    asm volatile("cp.async.wait_group 0;" ::: "memory");                      \
    __syncthreads();                                                          \
    {                                                                         \
        float *redb = (float *)smc;                                           \
        float *cf = &c[0][0][0];                                              \
        const int p_ = wid & 7;                                               \
        if (kg == 1) {                                                        \
            _Pragma("unroll") for (int j = 0; j < 32; j++)                    \
                redb[j * 256 + p_ * 32 + lane] = cf[j];                       \
        }                                                                     \
        __syncthreads();                                                      \
        if (kg == 0) {                                                        \
            _Pragma("unroll") for (int j = 0; j < 32; j++)                    \
                cf[j] += redb[j * 256 + p_ * 32 + lane];                      \
            float *Cout = C + (size_t)blockIdx.y * NNODES * HDIM;             \
            int crow = m0 + wm * 32 + (lane >> 2);                            \
            int ccol = wn * 32 + (lane & 3) * 2;                              \
            _Pragma("unroll") for (int mi = 0; mi < 2; mi++)                  \
                _Pragma("unroll") for (int nj = 0; nj < 4; nj++) {            \
                    int r = crow + mi * 16, cl = ccol + nj * 8;               \
                    *(float2 *)(Cout + (size_t)r * HDIM + cl) =               \
                        make_float2(c[mi][nj][0], c[mi][nj][1]);              \
                    *(float2 *)(Cout + (size_t)(r + 8) * HDIM + cl) =         \
                        make_float2(c[mi][nj][2], c[mi][nj][3]);              \
                }                                                             \
        }                                                                     \
        __syncthreads();                                                      \
    }

// last-CTA detection (writes slast for whole CTA)
#define GEMM_LAST(CNT)                                                        \
    __shared__ int slast;                                                     \
    __threadfence();                                                          \
    __syncthreads();                                                          \
    if (tid == 0) {                                                           \
        int old = atomicAdd(&(CNT)[blockIdx.x], 1);                           \
        slast = (old == 1);                                                   \
    }                                                                         \
    __syncthreads();                                                          \
    if (!slast) return;

// ---------------------------------------------------------------------------
// GEMM1 + fused mid epilogue (last CTA per row-block)
// ---------------------------------------------------------------------------
__global__ void __launch_bounds__(512, 1)
gemm1f(const __half *__restrict__ Ah, const __half *__restrict__ Bh,
       float *__restrict__ C, const float *__restrict__ b0,
       const float *__restrict__ g0, const float *__restrict__ be0,
       const float *__restrict__ W1) {
    GEMM_MAIN(Ah, Bh);
    GEMM_LAST(dCnt1);

    // epilogue = mid body over 128 rows (8 passes x 16 rows; warp = row)
    float4 *W1q = (float4 *)smc;                   // [16][64] = 16384 B
    float *hrow = (float *)(smc + 16384);          // [16][64] = 4096 B
    float *ybuf = (float *)(smc + 16384 + 4096);   // [16][68]
#pragma unroll
    for (int k = 0; k < 2; k++) {
        int p = tid + 512 * k;
        int t = p >> 6, n = p & 63;
        W1q[t * 64 + n] = make_float4(
            W1[(4 * t + 0) * HDIM + n], W1[(4 * t + 1) * HDIM + n],
            W1[(4 * t + 2) * HDIM + n], W1[(4 * t + 3) * HDIM + n]);
    }
    __syncthreads();

    float b0l = b0[lane], b0h = b0[lane + 32];
    float g0l = g0[lane], g0h = g0[lane + 32];
    float bel = be0[lane], beh = be0[lane + 32];
    for (int pass = 0; pass < 8; ++pass) {
        int row = m0 + pass * 16 + wid;
        float z0 = 0.f, z1 = 0.f;
#pragma unroll
        for (int s = 0; s < NSPLIT; s++) {
            const float *zp = dZP + (size_t)s * NNODES * HDIM + (size_t)row * HDIM;
            z0 += zp[lane];
            z1 += zp[lane + 32];
        }
        z0 = fmaxf(z0 * AINV + b0l, 0.f);
        z1 = fmaxf(z1 * AINV + b0h, 0.f);
        float s = z0 + z1;
#pragma unroll
        for (int o = 16; o > 0; o >>= 1) s += __shfl_xor_sync(0xffffffffu, s, o);
        float m = s * (1.f / 64.f);
        float d0 = z0 - m, d1 = z1 - m;
        float v = d0 * d0 + d1 * d1;
#pragma unroll
        for (int o = 16; o > 0; o >>= 1) v += __shfl_xor_sync(0xffffffffu, v, o);
        float rs = rsqrtf(v * (1.f / 64.f) + LNEPS);
        float h0a = d0 * rs * g0l + bel;
        float h0b = d1 * rs * g0h + beh;
        dH0[(size_t)row * HDIM + lane] = h0a;
        dH0[(size_t)row * HDIM + lane + 32] = h0b;
        hrow[wid * 64 + lane] = h0a;
        hrow[wid * 64 + lane + 32] = h0b;
        __syncwarp();
        float a0 = 0.f, a1 = 0.f;
        const float4 *h4 = (const float4 *)&hrow[wid * 64];
#pragma unroll
        for (int t = 0; t < 16; t++) {
            float4 h = h4[t];
            float4 wa = W1q[t * 64 + lane];
            float4 wb = W1q[t * 64 + lane + 32];
            a0 += h.x * wa.x + h.y * wa.y + h.z * wa.z + h.w * wa.w;
            a1 += h.x * wb.x + h.y * wb.y + h.z * wb.z + h.w * wb.w;
        }
        ybuf[wid * 68 + lane] = a0;
        ybuf[wid * 68 + lane + 32] = a1;
        __syncthreads();
#pragma unroll
        for (int k = 0; k < 2; k++) {
            int p = tid + 512 * k;
            int n = p >> 4, r = p & 15;
            dY1Th[(size_t)n * NNODES + m0 + pass * 16 + r] =
                __float2half_rn(ybuf[r * 68 + n]);
        }
        __syncthreads();
    }
}

// ---------------------------------------------------------------------------
// GEMM2 + fused epi2 epilogue (last CTA per row-block)
// ---------------------------------------------------------------------------
__global__ void __launch_bounds__(512, 1)
gemm2f(const __half *__restrict__ Ah, const __half *__restrict__ Bh,
       float *__restrict__ C, const int *__restrict__ I,
       const float *__restrict__ b1, const float *__restrict__ g1,
       const float *__restrict__ be1, const float *__restrict__ Wf,
       const float *__restrict__ bf, const float *__restrict__ Wa,
       const float *__restrict__ ba) {
    GEMM_MAIN(Ah, Bh);
    GEMM_LAST(dCnt2);

    float4 *Wfq = (float4 *)smc;                   // 16384 B
    float4 *Waq = (float4 *)(smc + 16384);         // 16384 B
    float *hrow = (float *)(smc + 32768);          // [16][64]
#pragma unroll
    for (int k = 0; k < 2; k++) {
        int p = tid + 512 * k;
        int t = p >> 6, n = p & 63;
        Wfq[t * 64 + n] = make_float4(
            Wf[(4 * t + 0) * HDIM + n], Wf[(4 * t + 1) * HDIM + n],
            Wf[(4 * t + 2) * HDIM + n], Wf[(4 * t + 3) * HDIM + n]);
        Waq[t * 64 + n] = make_float4(
            Wa[(4 * t + 0) * HDIM + n], Wa[(4 * t + 1) * HDIM + n],
            Wa[(4 * t + 2) * HDIM + n], Wa[(4 * t + 3) * HDIM + n]);
    }
    __syncthreads();

    float b1l = b1[lane], b1h = b1[lane + 32];
    float g1l = g1[lane], g1h = g1[lane + 32];
    float bel = be1[lane], beh = be1[lane + 32];
    float bfl = bf[lane], bfh = bf[lane + 32];
    float bal = ba[lane], bah = ba[lane + 32];
    for (int pass = 0; pass < 8; ++pass) {
        int row = m0 + pass * 16 + wid;
        float z0 = 0.f, z1 = 0.f;
#pragma unroll
        for (int s = 0; s < NSPLIT; s++) {
            const float *zp = dZP + (size_t)s * NNODES * HDIM + (size_t)row * HDIM;
            z0 += zp[lane];
            z1 += zp[lane + 32];
        }
        z0 = fmaxf(z0 * AINV + b1l, 0.f);
        z1 = fmaxf(z1 * AINV + b1h, 0.f);
        float s = z0 + z1;
#pragma unroll
        for (int o = 16; o > 0; o >>= 1) s += __shfl_xor_sync(0xffffffffu, s, o);
        float m = s * (1.f / 64.f);
        float d0 = z0 - m, d1 = z1 - m;
        float v = d0 * d0 + d1 * d1;
#pragma unroll
        for (int o = 16; o > 0; o >>= 1) v += __shfl_xor_sync(0xffffffffu, v, o);
        float rs = rsqrtf(v * (1.f / 64.f) + LNEPS);
        float ha = d0 * rs * g1l + bel + dH0[(size_t)row * HDIM + lane];
        float hb = d1 * rs * g1h + beh + dH0[(size_t)row * HDIM + lane + 32];
        hrow[wid * 64 + lane] = ha;
        hrow[wid * 64 + lane + 32] = hb;
        __syncwarp();
        float f0 = bfl, f1 = bfh, t0 = bal, t1 = bah;
        const float4 *h4 = (const float4 *)&hrow[wid * 64];
#pragma unroll
        for (int t = 0; t < 16; t++) {
            float4 h = h4[t];
            float4 fa = Wfq[t * 64 + lane];
            float4 fb = Wfq[t * 64 + lane + 32];
            float4 aa = Waq[t * 64 + lane];
            float4 ab = Waq[t * 64 + lane + 32];
            f0 += h.x * fa.x + h.y * fa.y + h.z * fa.z + h.w * fa.w;
            f1 += h.x * fb.x + h.y * fb.y + h.z * fb.z + h.w * fb.w;
            t0 += h.x * aa.x + h.y * aa.y + h.z * aa.z + h.w * aa.w;
            t1 += h.x * ab.x + h.y * ab.y + h.z * ab.z + h.w * ab.w;
        }
        t0 = 1.f / (1.f + expf(-t0));
        t1 = 1.f / (1.f + expf(-t1));
        int g = I[row];
        atomicAdd(&dG[g * HDIM + lane], f0 * t0);
        atomicAdd(&dG[g * HDIM + lane + 32], f1 * t1);
    }
}

// ---------------------------------------------------------------------------
// final: out[g] = [Gacc[g] | bary[g]] @ Wout + bout
// ---------------------------------------------------------------------------
__global__ void final_kernel(const float *__restrict__ Wout,
                             const float *__restrict__ bout, float *__restrict__ out) {
    int g = blockIdx.x * 64 + threadIdx.x;
    if (g >= GSEG) return;
    float a0 = bout[0], a1 = bout[1], a2 = bout[2];
#pragma unroll
    for (int j = 0; j < HDIM; j++) {
        float v = dG[g * HDIM + j];
        a0 += v * Wout[j * 3 + 0];
        a1 += v * Wout[j * 3 + 1];
        a2 += v * Wout[j * 3 + 2];
    }
    float zs = dZsum[g];
    float inv = zs > 0.f ? 1.f / zs : 0.f;
#pragma unroll
    for (int d = 0; d < 3; d++) {
        float b = dZnum[g * 3 + d] * inv;
        a0 += b * Wout[(HDIM + d) * 3 + 0];
        a1 += b * Wout[(HDIM + d) * 3 + 1];
        a2 += b * Wout[(HDIM + d) * 3 + 2];
    }
    out[g * 3 + 0] = a0;
    out[g * 3 + 1] = a1;
    out[g * 3 + 2] = a2;
}

// ---------------------------------------------------------------------------
// launch
// ---------------------------------------------------------------------------
extern "C" void kernel_launch(void *const *d_in, const int *in_sizes, int n_in,
                              void *d_out, int out_size) {
    const float *X = (const float *)d_in[0];
    const float *A = (const float *)d_in[1];
    const int *I = (const int *)d_in[2];
    const float *W0 = (const float *)d_in[3];
    const float *b0 = (const float *)d_in[4];
    const float *g0 = (const float *)d_in[5];
    const float *be0 = (const float *)d_in[6];
    const float *W1 = (const float *)d_in[7];
    const float *b1 = (const float *)d_in[8];
    const float *g1 = (const float *)d_in[9];
    const float *be1 = (const float *)d_in[10];
    const float *Wf = (const float *)d_in[11];
    const float *bf = (const float *)d_in[12];
    const float *Wa = (const float *)d_in[13];
    const float *ba = (const float *)d_in[14];
    const float *Wout = (const float *)d_in[15];
    const float *bout = (const float *)d_in[16];
    float *out = (float *)d_out;

    float *zp;
    __half *ah, *y0th, *y1th;
    cudaGetSymbolAddress((void **)&zp, dZP);
    cudaGetSymbolAddress((void **)&ah, dAh);
    cudaGetSymbolAddress((void **)&y0th, dY0Th);
    cudaGetSymbolAddress((void **)&y1th, dY1Th);

    cudaFuncSetAttribute(gemm1f, cudaFuncAttributeMaxDynamicSharedMemorySize, SMEM2);
    cudaFuncSetAttribute(gemm2f, cudaFuncAttributeMaxDynamicSharedMemorySize, SMEM2);

    prep_kernel<<<PREP_GRID, 256>>>(A, ah, X, W0, I);
    gemm1f<<<dim3(NNODES / BM, NSPLIT), 512, SMEM2>>>(ah, y0th, zp, b0, g0, be0, W1);
    gemm2f<<<dim3(NNODES / BM, NSPLIT), 512, SMEM2>>>(ah, y1th, zp, I, b1, g1, be1,
                                                      Wf, bf, Wa, ba);
    final_kernel<<<(GSEG + 63) / 64, 64>>>(Wout, bout, out);
}

// round 17
// speedup vs baseline: 1.1473x; 1.1473x over previous
#include <cuda_runtime.h>
#include <cuda_fp16.h>
#include <cstdint>
#include <math.h>

// ---------------------------------------------------------------------------
// Problem constants
// ---------------------------------------------------------------------------
#define NNODES 8192
#define FDIM   16
#define HDIM   64
#define GSEG   256
#define LNEPS  1e-3f
#define ASCALE 8192.0f
#define AINV   (1.0f / 8192.0f)

#define NSPLIT 2
#define KSPLIT (NNODES / NSPLIT)   // 4096
#define BM 128

// GEMM (fp16 m16n8k16, 512 threads, 16 warps: 4m x 2n x 2kg) -- R15 champion
#define BK2 64
#define NIT2 (KSPLIT / BK2)        // 64
#define LDH 72                     // half pitch (144 B), proven conflict-free
#define ST2A (BM * LDH * 2)        // 18432 B
#define ST2B (64 * LDH * 2)        // 9216 B
#define NST2 4
#define SMEM2 (NST2 * (ST2A + ST2B))   // 110592 B

// prep kernel block ranges
#define PREP_CONV 2048
#define PREP_Y0T  1024
#define PREP_GRID (PREP_CONV + PREP_Y0T + GSEG)   // 3328

// ---------------------------------------------------------------------------
// Device scratch
// ---------------------------------------------------------------------------
__device__ __half dAh[(size_t)NNODES * NNODES];   // A * 8192 fp16 (128 MB)
__device__ __half dY0Th[HDIM * NNODES];           // (X@W0)^T fp16
__device__ __half dY1Th[HDIM * NNODES];           // (h0@W1)^T fp16
__device__ float dZP[NSPLIT * NNODES * HDIM];     // split-K partials
__device__ float dH0[NNODES * HDIM];
__device__ float dG[GSEG * HDIM];
__device__ float dZsum[GSEG];
__device__ float dZnum[GSEG * 3];

// ---------------------------------------------------------------------------
// PTX helpers
// ---------------------------------------------------------------------------
__device__ __forceinline__ void cpa16(uint32_t dst, const void *src) {
    asm volatile("cp.async.cg.shared.global [%0], [%1], 16;" ::"r"(dst), "l"(src));
}
__device__ __forceinline__ void cpa_commit() {
    asm volatile("cp.async.commit_group;");
}
__device__ __forceinline__ void ldsm4(uint32_t &r0, uint32_t &r1, uint32_t &r2,
                                      uint32_t &r3, uint32_t addr) {
    asm volatile("ldmatrix.sync.aligned.m8n8.x4.shared.b16 {%0,%1,%2,%3}, [%4];"
                 : "=r"(r0), "=r"(r1), "=r"(r2), "=r"(r3) : "r"(addr));
}
__device__ __forceinline__ void mma_f16(float c[4], const uint32_t a[4],
                                        const uint32_t b[2]) {
    asm volatile(
        "mma.sync.aligned.m16n8k16.row.col.f32.f16.f16.f32 "
        "{%0,%1,%2,%3}, {%4,%5,%6,%7}, {%8,%9}, {%0,%1,%2,%3};"
        : "+f"(c[0]), "+f"(c[1]), "+f"(c[2]), "+f"(c[3])
        : "r"(a[0]), "r"(a[1]), "r"(a[2]), "r"(a[3]), "r"(b[0]), "r"(b[1]));
}

// ---------------------------------------------------------------------------
// prep: conv (Ah) + y0t (Y0Th) + zseg (stats + zero dG), one launch
// ---------------------------------------------------------------------------
__global__ void __launch_bounds__(256)
prep_kernel(const float *__restrict__ A, __half *__restrict__ Ah,
            const float *__restrict__ X, const float *__restrict__ W0,
            const int *__restrict__ I) {
    const int bid = blockIdx.x;
    const int tid = threadIdx.x;

    if (bid < PREP_CONV) {
        // ---- conv: stream A -> Ah ----
        const size_t stride = (size_t)PREP_CONV * 256 * 8;
        size_t base = ((size_t)bid * 256 + tid) * 8;
        const size_t total = (size_t)NNODES * NNODES;
        for (size_t i = base; i < total; i += stride) {
            float4 v0 = *(const float4 *)(A + i);
            float4 v1 = *(const float4 *)(A + i + 4);
            __half2 h[4];
            h[0] = __floats2half2_rn(v0.x * ASCALE, v0.y * ASCALE);
            h[1] = __floats2half2_rn(v0.z * ASCALE, v0.w * ASCALE);
            h[2] = __floats2half2_rn(v1.x * ASCALE, v1.y * ASCALE);
            h[3] = __floats2half2_rn(v1.z * ASCALE, v1.w * ASCALE);
            *(uint4 *)(Ah + i) = *(uint4 *)h;
        }
    } else if (bid < PREP_CONV + PREP_Y0T) {
        // ---- y0t ----
        __shared__ float W0s[FDIM][HDIM];
        __shared__ float ybuf[8][68];
        int lane = tid & 31, ty = tid >> 5;
#pragma unroll
        for (int j = 0; j < 4; j++) {
            int idx = tid + 256 * j;
            W0s[idx >> 6][idx & 63] = W0[idx];
        }
        __syncthreads();
        int row0 = (bid - PREP_CONV) * 8;
        int row = row0 + ty;
        float a0 = 0.f, a1 = 0.f;
#pragma unroll
        for (int f = 0; f < FDIM; f++) {
            float xf = X[row * FDIM + f];
            a0 += xf * W0s[f][lane];
            a1 += xf * W0s[f][lane + 32];
        }
        ybuf[ty][lane] = a0;
        ybuf[ty][lane + 32] = a1;
        __syncthreads();
#pragma unroll
        for (int k = 0; k < 2; k++) {
            int v = tid + 256 * k;
            int n = v >> 3, r = v & 7;
            dY0Th[(size_t)n * NNODES + row0 + r] = __float2half_rn(ybuf[r][n]);
        }
    } else {
        // ---- zseg + zero dG ----
        __shared__ int sb[2];
        __shared__ float red[256];
        int g = bid - (PREP_CONV + PREP_Y0T);
        int t = tid;
        if (t == 0) {
            int a = 0, b = NNODES;
            while (a < b) { int m = (a + b) >> 1; if (I[m] < g) a = m + 1; else b = m; }
            sb[0] = a;
            b = NNODES;
            while (a < b) { int m = (a + b) >> 1; if (I[m] < g + 1) a = m + 1; else b = m; }
            sb[1] = a;
        }
        if (t < HDIM) dG[g * HDIM + t] = 0.f;
        __syncthreads();
        int lo = sb[0], hi = sb[1];

        float zmax = 0.f;
        for (int i = lo + t; i < hi; i += 256)
            zmax = fmaxf(zmax, log1pf(fmaxf(X[i * FDIM], 0.f)));
        red[t] = zmax;
        __syncthreads();
        for (int s = 128; s > 0; s >>= 1) {
            if (t < s) red[t] = fmaxf(red[t], red[t + s]);
            __syncthreads();
        }
        zmax = red[0];
        __syncthreads();

        float se = 0.f, s0 = 0.f, s1 = 0.f, s2 = 0.f;
        for (int i = lo + t; i < hi; i += 256) {
            float z = log1pf(fmaxf(X[i * FDIM], 0.f));
            float w = expf(z - zmax);
            se += w;
            s0 += w * X[i * FDIM + 13];
            s1 += w * X[i * FDIM + 14];
            s2 += w * X[i * FDIM + 15];
        }
        float vals[4] = {se, s0, s1, s2};
#pragma unroll
        for (int q = 0; q < 4; q++) {
            red[t] = vals[q];
            __syncthreads();
            for (int s = 128; s > 0; s >>= 1) {
                if (t < s) red[t] += red[t + s];
                __syncthreads();
            }
            vals[q] = red[0];
            __syncthreads();
        }
        if (t == 0) {
            dZsum[g] = vals[0];
            dZnum[g * 3 + 0] = vals[1];
            dZnum[g * 3 + 1] = vals[2];
            dZnum[g * 3 + 2] = vals[3];
        }
    }
}

// ---------------------------------------------------------------------------
// GEMM (fp16, 512 thr, 16 warps = 4m x 2n x 2kg, in-CTA k-split + reduction)
//   dZP[y] = Ah[:, y*4096...] @ Bh^T   (scaled x8192)   -- R15 champion verbatim
// ---------------------------------------------------------------------------
__global__ void __launch_bounds__(512, 1)
gemm_f16(const __half *__restrict__ Ah, const __half *__restrict__ Bh,
         float *__restrict__ C) {
    extern __shared__ char smc[];
    char *As = smc;                       // [NST2][BM][LDH halfs]
    char *Bs = smc + NST2 * ST2A;         // [NST2][64][LDH halfs]

    const int tid = threadIdx.x;
    const int lane = tid & 31, wid = tid >> 5;
    const int wm = wid & 3;
    const int wn = (wid >> 2) & 1;
    const int kg = wid >> 3;              // k-group 0/1
    const int m0 = blockIdx.x * BM;
    const int kbeg = blockIdx.y * KSPLIT;

    float c[2][4][4] = {};

    const int arw = tid >> 3;             // 0..63
    const int ach = tid & 7;
    const __half *gA1 = Ah + (size_t)(m0 + arw) * NNODES + kbeg + ach * 8;
    const __half *gA2 = gA1 + (size_t)64 * NNODES;
    const uint32_t sA1 = (uint32_t)__cvta_generic_to_shared(As) + arw * (LDH * 2) + ach * 16;
    const uint32_t sA2 = sA1 + 64 * (LDH * 2);
    const __half *gB = Bh + (size_t)arw * NNODES + kbeg + ach * 8;
    const uint32_t sB = (uint32_t)__cvta_generic_to_shared(Bs) + arw * (LDH * 2) + ach * 16;

    const int arow = wm * 32 + (lane & 7) + ((lane >> 3) & 1) * 8;
    const int brow_ = wn * 32 + (lane & 7) + ((lane >> 3) & 1) * 8;
    const int kh = ((lane >> 4) & 1) * 8;

#define G_ISSUE(IT)                                                           \
    do {                                                                      \
        int buf = (IT) % NST2;                                                \
        size_t koff = (size_t)(IT) * BK2;                                     \
        cpa16(sA1 + buf * ST2A, gA1 + koff);                                  \
        cpa16(sA2 + buf * ST2A, gA2 + koff);                                  \
        cpa16(sB + buf * ST2B, gB + koff);                                    \
    } while (0)

#define G_COMPUTE(BUF)                                                        \
    do {                                                                      \
        uint32_t abase = (uint32_t)__cvta_generic_to_shared(As) + (BUF) * ST2A; \
        uint32_t bbase = (uint32_t)__cvta_generic_to_shared(Bs) + (BUF) * ST2B; \
        _Pragma("unroll") for (int kq = 0; kq < 2; kq++) {                    \
            int kb = (kg * 2 + kq) * 16 + kh;                                 \
            uint32_t a[2][4], b[4][2];                                        \
            _Pragma("unroll") for (int mi = 0; mi < 2; mi++) {                \
                uint32_t addr = abase + (arow + mi * 16) * (LDH * 2) + kb * 2; \
                ldsm4(a[mi][0], a[mi][1], a[mi][2], a[mi][3], addr);          \
            }                                                                 \
            _Pragma("unroll") for (int p = 0; p < 2; p++) {                   \
                uint32_t addr = bbase + (brow_ + p * 16) * (LDH * 2) + kb * 2; \
                uint32_t r0, r1, r2, r3;                                      \
                ldsm4(r0, r1, r2, r3, addr);                                  \
                b[p * 2][0] = r0; b[p * 2 + 1][0] = r1;                       \
                b[p * 2][1] = r2; b[p * 2 + 1][1] = r3;                       \
            }                                                                 \
            _Pragma("unroll") for (int mi = 0; mi < 2; mi++)                  \
                _Pragma("unroll") for (int nj = 0; nj < 4; nj++)              \
                    mma_f16(c[mi][nj], a[mi], b[nj]);                         \
        }                                                                     \
    } while (0)

#pragma unroll
    for (int s = 0; s < NST2 - 1; s++) {
        G_ISSUE(s);
        cpa_commit();
    }

    for (int it = 0; it < NIT2; ++it) {
        asm volatile("cp.async.wait_group 2;" ::: "memory");
        __syncthreads();
        if (it + NST2 - 1 < NIT2) G_ISSUE(it + NST2 - 1);
        cpa_commit();
        G_COMPUTE(it % NST2);
    }
    asm volatile("cp.async.wait_group 0;" ::: "memory");
    __syncthreads();

    // in-CTA k-split reduction: kg1 -> smem -> kg0 adds
    float *red = (float *)smc;            // [32][256] = 32 KB
    float *cf = &c[0][0][0];
    const int p_ = wid & 7;
    if (kg == 1) {
#pragma unroll
        for (int j = 0; j < 32; j++) red[j * 256 + p_ * 32 + lane] = cf[j];
    }
    __syncthreads();
    if (kg == 0) {
#pragma unroll
        for (int j = 0; j < 32; j++) cf[j] += red[j * 256 + p_ * 32 + lane];

        float *Cout = C + (size_t)blockIdx.y * NNODES * HDIM;
        int crow = m0 + wm * 32 + (lane >> 2);
        int ccol = wn * 32 + (lane & 3) * 2;
#pragma unroll
        for (int mi = 0; mi < 2; mi++)
#pragma unroll
            for (int nj = 0; nj < 4; nj++) {
                int r = crow + mi * 16, cl = ccol + nj * 8;
                *(float2 *)(Cout + (size_t)r * HDIM + cl) =
                    make_float2(c[mi][nj][0], c[mi][nj][1]);
                *(float2 *)(Cout + (size_t)(r + 8) * HDIM + cl) =
                    make_float2(c[mi][nj][2], c[mi][nj][3]);
            }
    }
#undef G_ISSUE
#undef G_COMPUTE
}

// ---------------------------------------------------------------------------
// mid: h0 = LN(relu(AINV*sum ZP + b0)); store h0 f32; Y1Th fp16
// ---------------------------------------------------------------------------
__global__ void __launch_bounds__(512)
mid_kernel(const float *__restrict__ b0, const float *__restrict__ g0,
           const float *__restrict__ be0, const float *__restrict__ W1) {
    __shared__ float4 W1q[16][64];
    __shared__ __align__(16) float hrow[16][HDIM];
    __shared__ float ybuf[16][68];
    int lane = threadIdx.x, ty = threadIdx.y;
    int tid = ty * 32 + lane;
#pragma unroll
    for (int k = 0; k < 2; k++) {
        int p = tid + 512 * k;
        int t = p >> 6, n = p & 63;
        W1q[t][n] = make_float4(W1[(4 * t + 0) * HDIM + n], W1[(4 * t + 1) * HDIM + n],
                                W1[(4 * t + 2) * HDIM + n], W1[(4 * t + 3) * HDIM + n]);
    }
    __syncthreads();

    int row0 = blockIdx.x * 16;
    int row = row0 + ty;
    float z0 = 0.f, z1 = 0.f;
#pragma unroll
    for (int s = 0; s < NSPLIT; s++) {
        const float *zp = dZP + (size_t)s * NNODES * HDIM + (size_t)row * HDIM;
        z0 += zp[lane];
        z1 += zp[lane + 32];
    }
    z0 = fmaxf(z0 * AINV + b0[lane], 0.f);
    z1 = fmaxf(z1 * AINV + b0[lane + 32], 0.f);
    float s = z0 + z1;
#pragma unroll
    for (int o = 16; o > 0; o >>= 1) s += __shfl_xor_sync(0xffffffffu, s, o);
    float m = s * (1.f / 64.f);
    float d0 = z0 - m, d1 = z1 - m;
    float v = d0 * d0 + d1 * d1;
#pragma unroll
    for (int o = 16; o > 0; o >>= 1) v += __shfl_xor_sync(0xffffffffu, v, o);
    float rs = rsqrtf(v * (1.f / 64.f) + LNEPS);
    float h0a = d0 * rs * g0[lane] + be0[lane];
    float h0b = d1 * rs * g0[lane + 32] + be0[lane + 32];
    dH0[(size_t)row * HDIM + lane] = h0a;
    dH0[(size_t)row * HDIM + lane + 32] = h0b;
    hrow[ty][lane] = h0a;
    hrow[ty][lane + 32] = h0b;
    __syncwarp();
    float a0 = 0.f, a1 = 0.f;
    const float4 *h4 = (const float4 *)&hrow[ty][0];
#pragma unroll
    for (int t = 0; t < 16; t++) {
        float4 h = h4[t];
        float4 wa = W1q[t][lane];
        float4 wb = W1q[t][lane + 32];
        a0 += h.x * wa.x + h.y * wa.y + h.z * wa.z + h.w * wa.w;
        a1 += h.x * wb.x + h.y * wb.y + h.z * wb.z + h.w * wb.w;
    }
    ybuf[ty][lane] = a0;
    ybuf[ty][lane + 32] = a1;
    __syncthreads();
#pragma unroll
    for (int k = 0; k < 2; k++) {
        int p = tid + 512 * k;
        int n = p >> 4, r = p & 15;
        dY1Th[(size_t)n * NNODES + row0 + r] = __float2half_rn(ybuf[r][n]);
    }
}

// ---------------------------------------------------------------------------
// epi2: h = LN(relu(AINV*sum ZP + b1)) + h0; feat/attn matvecs; seg atomics
// ---------------------------------------------------------------------------
__global__ void __launch_bounds__(512)
epi2_kernel(const int *__restrict__ I, const float *__restrict__ b1,
            const float *__restrict__ g1, const float *__restrict__ be1,
            const float *__restrict__ Wf, const float *__restrict__ bf,
            const float *__restrict__ Wa, const float *__restrict__ ba) {
    __shared__ float4 Wfq[16][64];
    __shared__ float4 Waq[16][64];
    __shared__ __align__(16) float hrow[16][HDIM];
    int lane = threadIdx.x, ty = threadIdx.y;
    int tid = ty * 32 + lane;
#pragma unroll
    for (int k = 0; k < 2; k++) {
        int p = tid + 512 * k;
        int t = p >> 6, n = p & 63;
        Wfq[t][n] = make_float4(Wf[(4 * t + 0) * HDIM + n], Wf[(4 * t + 1) * HDIM + n],
                                Wf[(4 * t + 2) * HDIM + n], Wf[(4 * t + 3) * HDIM + n]);
        Waq[t][n] = make_float4(Wa[(4 * t + 0) * HDIM + n], Wa[(4 * t + 1) * HDIM + n],
                                Wa[(4 * t + 2) * HDIM + n], Wa[(4 * t + 3) * HDIM + n]);
    }
    __syncthreads();

    int row = blockIdx.x * 16 + ty;
    float z0 = 0.f, z1 = 0.f;
#pragma unroll
    for (int s = 0; s < NSPLIT; s++) {
        const float *zp = dZP + (size_t)s * NNODES * HDIM + (size_t)row * HDIM;
        z0 += zp[lane];
        z1 += zp[lane + 32];
    }
    z0 = fmaxf(z0 * AINV + b1[lane], 0.f);
    z1 = fmaxf(z1 * AINV + b1[lane + 32], 0.f);
    float s = z0 + z1;
#pragma unroll
    for (int o = 16; o > 0; o >>= 1) s += __shfl_xor_sync(0xffffffffu, s, o);
    float m = s * (1.f / 64.f);
    float d0 = z0 - m, d1 = z1 - m;
    float v = d0 * d0 + d1 * d1;
#pragma unroll
    for (int o = 16; o > 0; o >>= 1) v += __shfl_xor_sync(0xffffffffu, v, o);
    float rs = rsqrtf(v * (1.f / 64.f) + LNEPS);
    float ha = d0 * rs * g1[lane] + be1[lane] + dH0[(size_t)row * HDIM + lane];
    float hb = d1 * rs * g1[lane + 32] + be1[lane + 32] + dH0[(size_t)row * HDIM + lane + 32];
    hrow[ty][lane] = ha;
    hrow[ty][lane + 32] = hb;
    __syncwarp();

    float f0 = bf[lane], f1 = bf[lane + 32];
    float t0 = ba[lane], t1 = ba[lane + 32];
    const float4 *h4 = (const float4 *)&hrow[ty][0];
#pragma unroll
    for (int t = 0; t < 16; t++) {
        float4 h = h4[t];
        float4 fa = Wfq[t][lane];
        float4 fb = Wfq[t][lane + 32];
        float4 aa = Waq[t][lane];
        float4 ab = Waq[t][lane + 32];
        f0 += h.x * fa.x + h.y * fa.y + h.z * fa.z + h.w * fa.w;
        f1 += h.x * fb.x + h.y * fb.y + h.z * fb.z + h.w * fb.w;
        t0 += h.x * aa.x + h.y * aa.y + h.z * aa.z + h.w * aa.w;
        t1 += h.x * ab.x + h.y * ab.y + h.z * ab.z + h.w * ab.w;
    }
    t0 = 1.f / (1.f + expf(-t0));
    t1 = 1.f / (1.f + expf(-t1));
    int g = I[row];
    atomicAdd(&dG[g * HDIM + lane], f0 * t0);
    atomicAdd(&dG[g * HDIM + lane + 32], f1 * t1);
}

// ---------------------------------------------------------------------------
// final: one block per graph; coalesced dG reads; block-reduce 3 dots
// ---------------------------------------------------------------------------
__global__ void __launch_bounds__(64)
final_kernel(const float *__restrict__ Wout, const float *__restrict__ bout,
             float *__restrict__ out) {
    __shared__ float r0s[64], r1s[64], r2s[64];
    int g = blockIdx.x;
    int t = threadIdx.x;   // 0..63
    float v = dG[g * HDIM + t];
    r0s[t] = v * Wout[t * 3 + 0];
    r1s[t] = v * Wout[t * 3 + 1];
    r2s[t] = v * Wout[t * 3 + 2];
    __syncthreads();
    for (int s = 32; s > 0; s >>= 1) {
        if (t < s) {
            r0s[t] += r0s[t + s];
            r1s[t] += r1s[t + s];
            r2s[t] += r2s[t + s];
        }
        __syncthreads();
    }
    if (t == 0) {
        float a0 = r0s[0] + bout[0];
        float a1 = r1s[0] + bout[1];
        float a2 = r2s[0] + bout[2];
        float zs = dZsum[g];
        float inv = zs > 0.f ? 1.f / zs : 0.f;
#pragma unroll
        for (int d = 0; d < 3; d++) {
            float b = dZnum[g * 3 + d] * inv;
            a0 += b * Wout[(HDIM + d) * 3 + 0];
            a1 += b * Wout[(HDIM + d) * 3 + 1];
            a2 += b * Wout[(HDIM + d) * 3 + 2];
        }
        out[g * 3 + 0] = a0;
        out[g * 3 + 1] = a1;
        out[g * 3 + 2] = a2;
    }
}

// ---------------------------------------------------------------------------
// launch
// ---------------------------------------------------------------------------
extern "C" void kernel_launch(void *const *d_in, const int *in_sizes, int n_in,
                              void *d_out, int out_size) {
    const float *X = (const float *)d_in[0];
    const float *A = (const float *)d_in[1];
    const int *I = (const int *)d_in[2];
    const float *W0 = (const float *)d_in[3];
    const float *b0 = (const float *)d_in[4];
    const float *g0 = (const float *)d_in[5];
    const float *be0 = (const float *)d_in[6];
    const float *W1 = (const float *)d_in[7];
    const float *b1 = (const float *)d_in[8];
    const float *g1 = (const float *)d_in[9];
    const float *be1 = (const float *)d_in[10];
    const float *Wf = (const float *)d_in[11];
    const float *bf = (const float *)d_in[12];
    const float *Wa = (const float *)d_in[13];
    const float *ba = (const float *)d_in[14];
    const float *Wout = (const float *)d_in[15];
    const float *bout = (const float *)d_in[16];
    float *out = (float *)d_out;

    float *zp;
    __half *ah, *y0th, *y1th;
    cudaGetSymbolAddress((void **)&zp, dZP);
    cudaGetSymbolAddress((void **)&ah, dAh);
    cudaGetSymbolAddress((void **)&y0th, dY0Th);
    cudaGetSymbolAddress((void **)&y1th, dY1Th);

    cudaFuncSetAttribute(gemm_f16, cudaFuncAttributeMaxDynamicSharedMemorySize, SMEM2);

    prep_kernel<<<PREP_GRID, 256>>>(A, ah, X, W0, I);
    gemm_f16<<<dim3(NNODES / BM, NSPLIT), 512, SMEM2>>>(ah, y0th, zp);
    mid_kernel<<<NNODES / 16, dim3(32, 16)>>>(b0, g0, be0, W1);
    gemm_f16<<<dim3(NNODES / BM, NSPLIT), 512, SMEM2>>>(ah, y1th, zp);
    epi2_kernel<<<NNODES / 16, dim3(32, 16)>>>(I, b1, g1, be1, Wf, bf, Wa, ba);
    final_kernel<<<GSEG, 64>>>(Wout, bout, out);
}